// round 13
// baseline (speedup 1.0000x reference)
#include <cuda_runtime.h>
#include <cuda_bf16.h>
#include <cstdint>

// Problem constants (fixed: T=128, B=64, D=4096, K_BITS=128)
#define N_ROWS 8192
#define DIMK   4096

// GEMM tiling: per block M=64 rows, N=128 bits, K-chunk 128 (int8). 512 threads, 16 warps 16x32.
#define BM 64
#define NTHR 512
#define KT 128
#define SKB 144                        // smem row stride bytes (128B int8 data + 16 pad; conflict-free LDSM)
#define L_STAGE (BM * SKB)             // 9216 B
#define A_STAGE (128 * SKB)            // 18432 B
#define A_BASE  (2 * L_STAGE)          // 18432
#define WSM_OFF (A_BASE + 2 * A_STAGE) // 55296
#define SMEM_BYTES (WSM_OFF + 1024)    // 56320 (dynamic)
#define CS_STRIDE 132                  // padded int32 C stride (aliases ring)
#define QSCALE 32.0f                   // fp32 -> int8 quantization scale

// Scratch (device globals; no allocation allowed)
__device__ uint4    g_keys[N_ROWS];
__device__ unsigned g_hash[N_ROWS];
__device__ int      g_cnt[N_ROWS];
__device__ unsigned g_Ai8[128 * DIMK / 4];   // A quantized to int8, packed 4/word

#define CP_ASYNC16(sa, ga) asm volatile("cp.async.cg.shared.global [%0], [%1], 16;\n" :: "r"(sa), "l"(ga))
#define CP_COMMIT()        asm volatile("cp.async.commit_group;\n" ::)
#define CP_WAIT0()         asm volatile("cp.async.wait_group 0;\n" ::)

__device__ __forceinline__ void ldsm4(unsigned r[4], unsigned addr) {
    asm volatile("ldmatrix.sync.aligned.m8n8.x4.shared.b16 {%0,%1,%2,%3}, [%4];\n"
                 : "=r"(r[0]), "=r"(r[1]), "=r"(r[2]), "=r"(r[3]) : "r"(addr));
}

// int8 tensor-core MMA: D(s32) += A(s8,16x32) * B(s8,32x8col)
__device__ __forceinline__ void mma_s8(int c[4], const unsigned a[4], unsigned b0, unsigned b1) {
    asm volatile(
        "mma.sync.aligned.m16n8k32.row.col.s32.s8.s8.s32 "
        "{%0,%1,%2,%3}, {%4,%5,%6,%7}, {%8,%9}, {%0,%1,%2,%3};\n"
        : "+r"(c[0]), "+r"(c[1]), "+r"(c[2]), "+r"(c[3])
        : "r"(a[0]), "r"(a[1]), "r"(a[2]), "r"(a[3]), "r"(b0), "r"(b1));
}

// Quantize float4 -> 4 saturated int8 packed in one word.
__device__ __forceinline__ unsigned pack_s8(float4 v) {
    int x0, x1, x2, x3;
    asm("cvt.rni.sat.s8.f32 %0, %1;" : "=r"(x0) : "f"(v.x * QSCALE));
    asm("cvt.rni.sat.s8.f32 %0, %1;" : "=r"(x1) : "f"(v.y * QSCALE));
    asm("cvt.rni.sat.s8.f32 %0, %1;" : "=r"(x2) : "f"(v.z * QSCALE));
    asm("cvt.rni.sat.s8.f32 %0, %1;" : "=r"(x3) : "f"(v.w * QSCALE));
    return (x0 & 0xFF) | ((x1 & 0xFF) << 8) | ((x2 & 0xFF) << 16) | ((unsigned)x3 << 24);
}

// Stage 0: pre-quantize fixed projection A to int8 (0.5 MB out).
__global__ void convertA_kernel(const float* __restrict__ A) {
    int i = blockIdx.x * 256 + threadIdx.x;   // over 128*4096/4 float4
    float4 v = reinterpret_cast<const float4*>(A)[i];
    g_Ai8[i] = pack_s8(v);
}

// Stage 1: int8 TC GEMM [64 x 128] per block -> sign-pack 128-bit keys + hash.
// Proven R5/R11 schedule (depth-1, 2-stage ring, per-iter sync); s8 halves
// fragment bytes per MAC and MMA count. NC=32, 4 k32-steps per iter.
__global__ __launch_bounds__(NTHR, 1)
void gemm_sign_kernel(const float* __restrict__ lat) {
    extern __shared__ __align__(16) char smem[];
    const unsigned sbase = (unsigned)__cvta_generic_to_shared(smem);

    const int tid  = threadIdx.x;
    const int lane = tid & 31;
    const int wid  = tid >> 5;       // 16 warps
    const int wm   = wid & 3;        // m tile (4 x 16 rows)
    const int wn   = wid >> 2;       // n tile (4 x 32 cols)
    const int rowBase = blockIdx.x * BM;

    // zero visit counters for this block's rows (graph-replay safe)
    if (tid < BM) g_cnt[rowBase + tid] = 0;

    int acc[4][4];
#pragma unroll
    for (int n = 0; n < 4; n++)
#pragma unroll
        for (int c = 0; c < 4; c++) acc[n][c] = 0;

    // --- per-thread cp.async coords for A (128 rows x 128 int8 = 16KB/slab) ---
    unsigned aso[2];
    const char* agb[2];
#pragma unroll
    for (int q = 0; q < 2; q++) {
        int f = tid + NTHR * q;        // 1024 x 16B chunks, 8 per row
        int row = f >> 3, ch = f & 7;
        aso[q] = sbase + A_BASE + row * SKB + ch * 16;
        agb[q] = reinterpret_cast<const char*>(g_Ai8) + (size_t)row * DIMK + ch * 16;
    }
#define ISSUE_A(slab) do { \
        unsigned _st = ((slab) & 1) * A_STAGE; \
        _Pragma("unroll") for (int q = 0; q < 2; q++) \
            CP_ASYNC16(aso[q] + _st, agb[q] + (size_t)(slab) * KT); \
        CP_COMMIT(); } while (0)

    // --- per-thread latent load coords (64 rows x 128 fp32 = 2048 float4) ---
    const char* latb = reinterpret_cast<const char*>(lat);
    unsigned lgo[4], lso[4];
#pragma unroll
    for (int q = 0; q < 4; q++) {
        int f = tid + NTHR * q;        // 32 float4 per row
        int r = f >> 5, c = f & 31;
        lgo[q] = (unsigned)(((rowBase + r) * DIMK + c * 4) * 4);   // byte offset (fits 32-bit)
        lso[q] = r * SKB + c * 4;      // int8 byte offset: float4 chunk -> 4 bytes
    }

    // --- prologue: A slab 0 in flight; latent slab 0 in regs ---
    ISSUE_A(0);
    float4 rl[4];
#pragma unroll
    for (int q = 0; q < 4; q++)
        rl[q] = *reinterpret_cast<const float4*>(latb + lgo[q]);

    // ldmatrix base addresses (lane-dependent; stage offset added per iter)
    const unsigned lmb = sbase + (wm * 16 + (lane & 15)) * SKB + (lane >> 4) * 16;
    const unsigned amb = sbase + A_BASE
                       + (wn * 32 + (lane & 7) + ((lane >> 4) << 3)) * SKB
                       + ((lane >> 3) & 1) * 16;

    const int NC = DIMK / KT;  // 32
    for (int kc = 0; kc < NC; kc++) {
        const int ls = kc & 1;
        // quantize + store latent slab kc
        char* Ls = smem + ls * L_STAGE;
#pragma unroll
        for (int q = 0; q < 4; q++)
            *reinterpret_cast<unsigned*>(Ls + lso[q]) = pack_s8(rl[q]);
        CP_WAIT0();          // A slab kc resident
        __syncthreads();     // + all LDSM of slab kc-1 complete

        if (kc + 1 < NC) {
            // A stage (kc+1)&1 last read by MMA(kc-1); ordered by the sync above
            ISSUE_A(kc + 1);
            const unsigned k0 = (unsigned)(kc + 1) * KT * 4;   // byte advance in fp32 latent
#pragma unroll
            for (int q = 0; q < 4; q++)
                rl[q] = *reinterpret_cast<const float4*>(latb + lgo[q] + k0);
        }

        const unsigned lb = lmb + ls * L_STAGE;
        const unsigned ab = amb + ls * A_STAGE;
#pragma unroll
        for (int ks = 0; ks < 4; ks++) {   // 4 x k32
            unsigned a[4], b0[4], b1[4];
            ldsm4(a,  lb + ks * 32);
            ldsm4(b0, ab + ks * 32);
            ldsm4(b1, ab + 16 * SKB + ks * 32);
            mma_s8(acc[0], a, b0[0], b0[1]);
            mma_s8(acc[1], a, b0[2], b0[3]);
            mma_s8(acc[2], a, b1[0], b1[1]);
            mma_s8(acc[3], a, b1[2], b1[3]);
        }
        // no tail sync: next STS targets the other L stage; A issue ordered by next sync
    }
    __syncthreads();   // all MMA smem reads done before aliasing C over the buffers

    // --- epilogue: C (s32) -> smem (padded), ballot sign-pack, key + hash ---
    int*      Cs  = reinterpret_cast<int*>(smem);
    unsigned* wsm = reinterpret_cast<unsigned*>(smem + WSM_OFF);
    const int g = lane >> 2, tig = lane & 3;
#pragma unroll
    for (int ni = 0; ni < 4; ni++) {
        int row = wm * 16 + g;
        int col = wn * 32 + ni * 8 + 2 * tig;
        *reinterpret_cast<int2*>(&Cs[row * CS_STRIDE + col])       = make_int2(acc[ni][0], acc[ni][1]);
        *reinterpret_cast<int2*>(&Cs[(row + 8) * CS_STRIDE + col]) = make_int2(acc[ni][2], acc[ni][3]);
    }
    __syncthreads();

    // 256 words (64 rows x 4); 16 warps x 16 words; ballot packs 32 signs/instr
#pragma unroll
    for (int t = 0; t < 16; t++) {
        int idx = wid * 16 + t;
        int row = idx >> 2, w = idx & 3;
        unsigned bits = __ballot_sync(0xffffffffu, Cs[row * CS_STRIDE + w * 32 + lane] > 0);
        if (lane == 0) {
            wsm[idx] = bits;
            reinterpret_cast<unsigned*>(g_keys)[(size_t)(rowBase + row) * 4 + w] = bits;
        }
    }
    __syncthreads();

    if (tid < BM) {
        unsigned w0 = wsm[tid * 4 + 0], w1 = wsm[tid * 4 + 1];
        unsigned w2 = wsm[tid * 4 + 2], w3 = wsm[tid * 4 + 3];
        unsigned h = w0 * 0x9E3779B1u;
        h ^= w1; h *= 0x85EBCA77u;
        h ^= w2; h *= 0xC2B2AE3Du;
        h ^= w3; h *= 0x27D4EB2Fu;
        h ^= h >> 15;
        g_hash[rowBase + tid] = h;
    }
}

// Stage 2: tile-parallel prefix-duplicate count (lower-triangle 256x256 tiles).
#define TI 256
__global__ __launch_bounds__(TI, 8)
void count_tile_kernel() {
    const int ti = blockIdx.y, tj = blockIdx.x;
    if (tj > ti) return;

    __shared__ __align__(16) unsigned shh[TI];
    const int tid   = threadIdx.x;
    const int i     = ti * TI + tid;
    const int jbase = tj * TI;

    shh[tid] = g_hash[jbase + tid];
    const unsigned hi = g_hash[i];
    const uint4    ki = g_keys[i];
    __syncthreads();

    const int lim = (ti == tj) ? (tid + 1) : TI;
    const int l4  = lim & ~3;
    int cnt = 0;

    const uint4* sh4 = reinterpret_cast<const uint4*>(shh);
    for (int j = 0; j < l4; j += 4) {
        uint4 hv = sh4[j >> 2];
        if (hv.x == hi) { uint4 kj = g_keys[jbase + j    ]; cnt += (kj.x==ki.x && kj.y==ki.y && kj.z==ki.z && kj.w==ki.w); }
        if (hv.y == hi) { uint4 kj = g_keys[jbase + j + 1]; cnt += (kj.x==ki.x && kj.y==ki.y && kj.z==ki.z && kj.w==ki.w); }
        if (hv.z == hi) { uint4 kj = g_keys[jbase + j + 2]; cnt += (kj.x==ki.x && kj.y==ki.y && kj.z==ki.z && kj.w==ki.w); }
        if (hv.w == hi) { uint4 kj = g_keys[jbase + j + 3]; cnt += (kj.x==ki.x && kj.y==ki.y && kj.z==ki.z && kj.w==ki.w); }
    }
    for (int j = l4; j < lim; j++) {
        if (shh[j] == hi) {
            uint4 kj = g_keys[jbase + j];
            cnt += (kj.x==ki.x && kj.y==ki.y && kj.z==ki.z && kj.w==ki.w);
        }
    }

    if (cnt) atomicAdd(&g_cnt[i], cnt);
}

// Stage 3: finalize — intrinsic reward.
__global__ void finalize_kernel(float* __restrict__ out) {
    int i = blockIdx.x * 256 + threadIdx.x;
    out[i] = rsqrtf((float)g_cnt[i]);
}

extern "C" void kernel_launch(void* const* d_in, const int* in_sizes, int n_in,
                              void* d_out, int out_size) {
    const float* lat  = (const float*)d_in[0];   // [128,64,4096]
    const float* Amat = (const float*)d_in[1];   // [128,4096]
    float* out = (float*)d_out;                  // [T,B] fp32

    cudaFuncSetAttribute(gemm_sign_kernel,
                         cudaFuncAttributeMaxDynamicSharedMemorySize, SMEM_BYTES);

    convertA_kernel<<<(128 * DIMK / 4) / 256, 256>>>(Amat);
    gemm_sign_kernel<<<N_ROWS / BM, NTHR, SMEM_BYTES>>>(lat);
    dim3 cgrid(N_ROWS / TI, N_ROWS / TI);
    count_tile_kernel<<<cgrid, TI>>>();
    finalize_kernel<<<N_ROWS / 256, 256>>>(out);
}

// round 14
// speedup vs baseline: 1.5819x; 1.5819x over previous
#include <cuda_runtime.h>
#include <cuda_bf16.h>
#include <cstdint>

// Problem constants (fixed: T=128, B=64, D=4096, K_BITS=128)
#define N_ROWS 8192
#define DIMK   4096

// GEMM tiling: per block M=64 rows, N=128 bits, K-chunk 128. 512 threads, 16 warps 16x32.
#define BM 64
#define NTHR 512
#define KT 128
#define SKB 272                        // smem row stride bytes (256B data + 16 pad; conflict-free LDSM)
#define L_STAGE (BM * SKB)             // 17408 B
#define A_STAGE (128 * SKB)            // 34816 B
#define A_BASE  (2 * L_STAGE)          // 34816
#define WSM_OFF (A_BASE + 2 * A_STAGE) // 104448
#define SMEM_BYTES (WSM_OFF + 1024)    // 105472 (dynamic)
#define CS_STRIDE 132                  // padded fp32 C stride (aliases ring)

// Scratch (device globals; no allocation allowed)
__device__ uint4         g_keys[N_ROWS];
__device__ unsigned      g_hash[N_ROWS];
__device__ int           g_cnt[N_ROWS];
__device__ __nv_bfloat16 g_Abf[128 * DIMK];

#define CP_ASYNC16(sa, ga) asm volatile("cp.async.cg.shared.global [%0], [%1], 16;\n" :: "r"(sa), "l"(ga))
#define CP_COMMIT()        asm volatile("cp.async.commit_group;\n" ::)
#define CP_WAIT0()         asm volatile("cp.async.wait_group 0;\n" ::)

__device__ __forceinline__ void ldsm4(unsigned r[4], unsigned addr) {
    asm volatile("ldmatrix.sync.aligned.m8n8.x4.shared.b16 {%0,%1,%2,%3}, [%4];\n"
                 : "=r"(r[0]), "=r"(r[1]), "=r"(r[2]), "=r"(r[3]) : "r"(addr));
}

__device__ __forceinline__ void mma_bf16(float c[4], const unsigned a[4], unsigned b0, unsigned b1) {
    asm volatile(
        "mma.sync.aligned.m16n8k16.row.col.f32.bf16.bf16.f32 "
        "{%0,%1,%2,%3}, {%4,%5,%6,%7}, {%8,%9}, {%0,%1,%2,%3};\n"
        : "+f"(c[0]), "+f"(c[1]), "+f"(c[2]), "+f"(c[3])
        : "r"(a[0]), "r"(a[1]), "r"(a[2]), "r"(a[3]), "r"(b0), "r"(b1));
}

// Stage 0: pre-convert fixed projection A to bf16 (proven 512-block version).
__global__ void convertA_kernel(const float* __restrict__ A) {
    int i = blockIdx.x * 256 + threadIdx.x;   // over 128*4096/4 float4
    float4 v = reinterpret_cast<const float4*>(A)[i];
    __nv_bfloat162 h0 = __floats2bfloat162_rn(v.x, v.y);
    __nv_bfloat162 h1 = __floats2bfloat162_rn(v.z, v.w);
    uint2 p;
    p.x = reinterpret_cast<unsigned&>(h0);
    p.y = reinterpret_cast<unsigned&>(h1);
    reinterpret_cast<uint2*>(g_Abf)[i] = p;
}

// Stage 1: bf16 TC GEMM [64 x 128] per block -> sign-pack 128-bit keys + hash.
// Proven champion (R11): depth-1, 2-stage ring, KT=128, per-iter sync.
// Micro-fix: latent LDG for slab kc+1 hoisted BEFORE the wait+barrier
// (registers only; their prior value was consumed by the STS just above).
__global__ __launch_bounds__(NTHR, 1)
void gemm_sign_kernel(const float* __restrict__ lat) {
    extern __shared__ __align__(16) char smem[];
    const unsigned sbase = (unsigned)__cvta_generic_to_shared(smem);

    const int tid  = threadIdx.x;
    const int lane = tid & 31;
    const int wid  = tid >> 5;       // 16 warps
    const int wm   = wid & 3;        // m tile (4 x 16 rows)
    const int wn   = wid >> 2;       // n tile (4 x 32 cols)
    const int rowBase = blockIdx.x * BM;

    // zero visit counters for this block's rows (graph-replay safe)
    if (tid < BM) g_cnt[rowBase + tid] = 0;

    float acc[4][4];
#pragma unroll
    for (int n = 0; n < 4; n++)
#pragma unroll
        for (int c = 0; c < 4; c++) acc[n][c] = 0.f;

    // --- per-thread cp.async coords for A (128 rows x 128 bf16 = 32KB/slab) ---
    unsigned aso[4];
    const __nv_bfloat16* agb[4];
#pragma unroll
    for (int q = 0; q < 4; q++) {
        int f = tid + NTHR * q;        // 2048 x 16B chunks, 16 per row
        int row = f >> 4, ch = f & 15;
        aso[q] = sbase + A_BASE + row * SKB + ch * 16;
        agb[q] = g_Abf + (size_t)row * DIMK + ch * 8;
    }
#define ISSUE_A(slab) do { \
        unsigned _st = ((slab) & 1) * A_STAGE; \
        _Pragma("unroll") for (int q = 0; q < 4; q++) \
            CP_ASYNC16(aso[q] + _st, agb[q] + (size_t)(slab) * KT); \
        CP_COMMIT(); } while (0)

    // --- per-thread latent load coords (64 rows x 128 fp32 = 2048 float4) ---
    const char* latb = reinterpret_cast<const char*>(lat);
    unsigned lgo[4], lso[4];
#pragma unroll
    for (int q = 0; q < 4; q++) {
        int f = tid + NTHR * q;        // 32 float4 per row
        int r = f >> 5, c = f & 31;
        lgo[q] = (unsigned)(((rowBase + r) * DIMK + c * 4) * 4);   // byte offset (fits 32-bit)
        lso[q] = r * SKB + c * 8;      // bf16 byte offset: chunk c -> 8 bytes
    }

    // --- prologue: A slab 0 in flight; latent slab 0 in regs ---
    ISSUE_A(0);
    float4 rl[4];
#pragma unroll
    for (int q = 0; q < 4; q++)
        rl[q] = *reinterpret_cast<const float4*>(latb + lgo[q]);

    // ldmatrix base addresses (lane-dependent; stage offset added per iter)
    const unsigned lmb = sbase + (wm * 16 + (lane & 15)) * SKB + (lane >> 4) * 16;
    const unsigned amb = sbase + A_BASE
                       + (wn * 32 + (lane & 7) + ((lane >> 4) << 3)) * SKB
                       + ((lane >> 3) & 1) * 16;

    const int NC = DIMK / KT;  // 32
    for (int kc = 0; kc < NC; kc++) {
        const int ls = kc & 1;
        // convert + store latent slab kc (consumes rl)
        char* Ls = smem + ls * L_STAGE;
#pragma unroll
        for (int q = 0; q < 4; q++) {
            __nv_bfloat162 h0 = __floats2bfloat162_rn(rl[q].x, rl[q].y);
            __nv_bfloat162 h1 = __floats2bfloat162_rn(rl[q].z, rl[q].w);
            uint2 pv;
            pv.x = reinterpret_cast<unsigned&>(h0);
            pv.y = reinterpret_cast<unsigned&>(h1);
            *reinterpret_cast<uint2*>(Ls + lso[q]) = pv;
        }
        // HOIST: issue latent LDG for slab kc+1 before the wait+barrier
        // (targets registers only; prior value consumed by the STS above)
        if (kc + 1 < NC) {
            const unsigned k0 = (unsigned)(kc + 1) * KT * 4;   // byte advance
#pragma unroll
            for (int q = 0; q < 4; q++)
                rl[q] = *reinterpret_cast<const float4*>(latb + lgo[q] + k0);
        }
        CP_WAIT0();          // A slab kc resident
        __syncthreads();     // + all LDSM of slab kc-1 complete

        // A stage (kc+1)&1 last read by MMA(kc-1); ordered by the sync above
        if (kc + 1 < NC) ISSUE_A(kc + 1);

        const unsigned lb = lmb + ls * L_STAGE;
        const unsigned ab = amb + ls * A_STAGE;
#pragma unroll
        for (int ks = 0; ks < 8; ks++) {
            unsigned a[4], b0[4], b1[4];
            ldsm4(a,  lb + ks * 32);
            ldsm4(b0, ab + ks * 32);
            ldsm4(b1, ab + 16 * SKB + ks * 32);
            mma_bf16(acc[0], a, b0[0], b0[1]);
            mma_bf16(acc[1], a, b0[2], b0[3]);
            mma_bf16(acc[2], a, b1[0], b1[1]);
            mma_bf16(acc[3], a, b1[2], b1[3]);
        }
        // no tail sync: next STS targets the other L stage; A issue ordered by next sync
    }
    __syncthreads();   // all MMA smem reads done before aliasing C over the buffers

    // --- epilogue: C -> smem (padded), ballot sign-pack, key + hash ---
    float*    Cs  = reinterpret_cast<float*>(smem);
    unsigned* wsm = reinterpret_cast<unsigned*>(smem + WSM_OFF);
    const int g = lane >> 2, tig = lane & 3;
#pragma unroll
    for (int ni = 0; ni < 4; ni++) {
        int row = wm * 16 + g;
        int col = wn * 32 + ni * 8 + 2 * tig;
        *reinterpret_cast<float2*>(&Cs[row * CS_STRIDE + col])       = make_float2(acc[ni][0], acc[ni][1]);
        *reinterpret_cast<float2*>(&Cs[(row + 8) * CS_STRIDE + col]) = make_float2(acc[ni][2], acc[ni][3]);
    }
    __syncthreads();

    // 256 words (64 rows x 4); 16 warps x 16 words; ballot packs 32 signs/instr
#pragma unroll
    for (int t = 0; t < 16; t++) {
        int idx = wid * 16 + t;
        int row = idx >> 2, w = idx & 3;
        unsigned bits = __ballot_sync(0xffffffffu, Cs[row * CS_STRIDE + w * 32 + lane] > 0.0f);
        if (lane == 0) {
            wsm[idx] = bits;
            reinterpret_cast<unsigned*>(g_keys)[(size_t)(rowBase + row) * 4 + w] = bits;
        }
    }
    __syncthreads();

    if (tid < BM) {
        unsigned w0 = wsm[tid * 4 + 0], w1 = wsm[tid * 4 + 1];
        unsigned w2 = wsm[tid * 4 + 2], w3 = wsm[tid * 4 + 3];
        unsigned h = w0 * 0x9E3779B1u;
        h ^= w1; h *= 0x85EBCA77u;
        h ^= w2; h *= 0xC2B2AE3Du;
        h ^= w3; h *= 0x27D4EB2Fu;
        h ^= h >> 15;
        g_hash[rowBase + tid] = h;
    }
}

// Stage 2: tile-parallel prefix-duplicate count (lower-triangle 256x256 tiles).
#define TI 256
__global__ __launch_bounds__(TI, 8)
void count_tile_kernel() {
    const int ti = blockIdx.y, tj = blockIdx.x;
    if (tj > ti) return;

    __shared__ __align__(16) unsigned shh[TI];
    const int tid   = threadIdx.x;
    const int i     = ti * TI + tid;
    const int jbase = tj * TI;

    shh[tid] = g_hash[jbase + tid];
    const unsigned hi = g_hash[i];
    const uint4    ki = g_keys[i];
    __syncthreads();

    const int lim = (ti == tj) ? (tid + 1) : TI;
    const int l4  = lim & ~3;
    int cnt = 0;

    const uint4* sh4 = reinterpret_cast<const uint4*>(shh);
    for (int j = 0; j < l4; j += 4) {
        uint4 hv = sh4[j >> 2];
        if (hv.x == hi) { uint4 kj = g_keys[jbase + j    ]; cnt += (kj.x==ki.x && kj.y==ki.y && kj.z==ki.z && kj.w==ki.w); }
        if (hv.y == hi) { uint4 kj = g_keys[jbase + j + 1]; cnt += (kj.x==ki.x && kj.y==ki.y && kj.z==ki.z && kj.w==ki.w); }
        if (hv.z == hi) { uint4 kj = g_keys[jbase + j + 2]; cnt += (kj.x==ki.x && kj.y==ki.y && kj.z==ki.z && kj.w==ki.w); }
        if (hv.w == hi) { uint4 kj = g_keys[jbase + j + 3]; cnt += (kj.x==ki.x && kj.y==ki.y && kj.z==ki.z && kj.w==ki.w); }
    }
    for (int j = l4; j < lim; j++) {
        if (shh[j] == hi) {
            uint4 kj = g_keys[jbase + j];
            cnt += (kj.x==ki.x && kj.y==ki.y && kj.z==ki.z && kj.w==ki.w);
        }
    }

    if (cnt) atomicAdd(&g_cnt[i], cnt);
}

// Stage 3: finalize — intrinsic reward.
__global__ void finalize_kernel(float* __restrict__ out) {
    int i = blockIdx.x * 256 + threadIdx.x;
    out[i] = rsqrtf((float)g_cnt[i]);
}

extern "C" void kernel_launch(void* const* d_in, const int* in_sizes, int n_in,
                              void* d_out, int out_size) {
    const float* lat  = (const float*)d_in[0];   // [128,64,4096]
    const float* Amat = (const float*)d_in[1];   // [128,4096]
    float* out = (float*)d_out;                  // [T,B] fp32

    cudaFuncSetAttribute(gemm_sign_kernel,
                         cudaFuncAttributeMaxDynamicSharedMemorySize, SMEM_BYTES);

    convertA_kernel<<<(128 * DIMK / 4) / 256, 256>>>(Amat);
    gemm_sign_kernel<<<N_ROWS / BM, NTHR, SMEM_BYTES>>>(lat);
    dim3 cgrid(N_ROWS / TI, N_ROWS / TI);
    count_tile_kernel<<<cgrid, TI>>>();
    finalize_kernel<<<N_ROWS / 256, 256>>>(out);
}

// round 15
// speedup vs baseline: 1.5882x; 1.0040x over previous
#include <cuda_runtime.h>
#include <cuda_bf16.h>
#include <cstdint>

// Problem constants (fixed: T=128, B=64, D=4096, K_BITS=128)
#define N_ROWS 8192
#define DIMK   4096

// GEMM tiling: per block M=64 rows, N=128 bits, K-chunk 128. 512 threads, 16 warps 16x32.
#define BM 64
#define NTHR 512
#define KT 128
#define SKB 272                        // smem row stride bytes (256B data + 16 pad; conflict-free LDSM)
#define L_STAGE (BM * SKB)             // 17408 B
#define A_STAGE (128 * SKB)            // 34816 B
#define A_BASE  (2 * L_STAGE)          // 34816
#define WSM_OFF (A_BASE + 2 * A_STAGE) // 104448
#define SMEM_BYTES (WSM_OFF + 1024)    // 105472 (dynamic)
#define CS_STRIDE 132                  // padded fp32 C stride (aliases ring)
#define TI 256                         // count tile size

// Scratch (device globals; no allocation allowed)
__device__ uint4         g_keys[N_ROWS];
__device__ unsigned      g_hash[N_ROWS];
__device__ int           g_cnt[N_ROWS];
__device__ int           g_tile_done[N_ROWS / TI];
__device__ __nv_bfloat16 g_Abf[128 * DIMK];

#define CP_ASYNC16(sa, ga) asm volatile("cp.async.cg.shared.global [%0], [%1], 16;\n" :: "r"(sa), "l"(ga))
#define CP_COMMIT()        asm volatile("cp.async.commit_group;\n" ::)
#define CP_WAIT0()         asm volatile("cp.async.wait_group 0;\n" ::)

__device__ __forceinline__ void ldsm4(unsigned r[4], unsigned addr) {
    asm volatile("ldmatrix.sync.aligned.m8n8.x4.shared.b16 {%0,%1,%2,%3}, [%4];\n"
                 : "=r"(r[0]), "=r"(r[1]), "=r"(r[2]), "=r"(r[3]) : "r"(addr));
}

__device__ __forceinline__ void mma_bf16(float c[4], const unsigned a[4], unsigned b0, unsigned b1) {
    asm volatile(
        "mma.sync.aligned.m16n8k16.row.col.f32.bf16.bf16.f32 "
        "{%0,%1,%2,%3}, {%4,%5,%6,%7}, {%8,%9}, {%0,%1,%2,%3};\n"
        : "+f"(c[0]), "+f"(c[1]), "+f"(c[2]), "+f"(c[3])
        : "r"(a[0]), "r"(a[1]), "r"(a[2]), "r"(a[3]), "r"(b0), "r"(b1));
}

// Stage 0: pre-convert fixed projection A to bf16 (proven 512-block version).
__global__ void convertA_kernel(const float* __restrict__ A) {
    int i = blockIdx.x * 256 + threadIdx.x;   // over 128*4096/4 float4
    float4 v = reinterpret_cast<const float4*>(A)[i];
    __nv_bfloat162 h0 = __floats2bfloat162_rn(v.x, v.y);
    __nv_bfloat162 h1 = __floats2bfloat162_rn(v.z, v.w);
    uint2 p;
    p.x = reinterpret_cast<unsigned&>(h0);
    p.y = reinterpret_cast<unsigned&>(h1);
    reinterpret_cast<uint2*>(g_Abf)[i] = p;
}

// Stage 1: bf16 TC GEMM [64 x 128] per block -> sign-pack 128-bit keys + hash.
// Champion (R14): depth-1, 2-stage ring, KT=128, hoisted latent LDG.
__global__ __launch_bounds__(NTHR, 1)
void gemm_sign_kernel(const float* __restrict__ lat) {
    extern __shared__ __align__(16) char smem[];
    const unsigned sbase = (unsigned)__cvta_generic_to_shared(smem);

    const int tid  = threadIdx.x;
    const int lane = tid & 31;
    const int wid  = tid >> 5;       // 16 warps
    const int wm   = wid & 3;        // m tile (4 x 16 rows)
    const int wn   = wid >> 2;       // n tile (4 x 32 cols)
    const int rowBase = blockIdx.x * BM;

    // zero per-row and per-tile counters (graph-replay safe; gemm precedes count)
    if (tid < BM) g_cnt[rowBase + tid] = 0;
    if (blockIdx.x < N_ROWS / TI && tid == 0) g_tile_done[blockIdx.x] = 0;

    float acc[4][4];
#pragma unroll
    for (int n = 0; n < 4; n++)
#pragma unroll
        for (int c = 0; c < 4; c++) acc[n][c] = 0.f;

    // --- per-thread cp.async coords for A (128 rows x 128 bf16 = 32KB/slab) ---
    unsigned aso[4];
    const __nv_bfloat16* agb[4];
#pragma unroll
    for (int q = 0; q < 4; q++) {
        int f = tid + NTHR * q;        // 2048 x 16B chunks, 16 per row
        int row = f >> 4, ch = f & 15;
        aso[q] = sbase + A_BASE + row * SKB + ch * 16;
        agb[q] = g_Abf + (size_t)row * DIMK + ch * 8;
    }
#define ISSUE_A(slab) do { \
        unsigned _st = ((slab) & 1) * A_STAGE; \
        _Pragma("unroll") for (int q = 0; q < 4; q++) \
            CP_ASYNC16(aso[q] + _st, agb[q] + (size_t)(slab) * KT); \
        CP_COMMIT(); } while (0)

    // --- per-thread latent load coords (64 rows x 128 fp32 = 2048 float4) ---
    const char* latb = reinterpret_cast<const char*>(lat);
    unsigned lgo[4], lso[4];
#pragma unroll
    for (int q = 0; q < 4; q++) {
        int f = tid + NTHR * q;        // 32 float4 per row
        int r = f >> 5, c = f & 31;
        lgo[q] = (unsigned)(((rowBase + r) * DIMK + c * 4) * 4);   // byte offset (fits 32-bit)
        lso[q] = r * SKB + c * 8;      // bf16 byte offset: chunk c -> 8 bytes
    }

    // --- prologue: A slab 0 in flight; latent slab 0 in regs ---
    ISSUE_A(0);
    float4 rl[4];
#pragma unroll
    for (int q = 0; q < 4; q++)
        rl[q] = *reinterpret_cast<const float4*>(latb + lgo[q]);

    // ldmatrix base addresses (lane-dependent; stage offset added per iter)
    const unsigned lmb = sbase + (wm * 16 + (lane & 15)) * SKB + (lane >> 4) * 16;
    const unsigned amb = sbase + A_BASE
                       + (wn * 32 + (lane & 7) + ((lane >> 4) << 3)) * SKB
                       + ((lane >> 3) & 1) * 16;

    const int NC = DIMK / KT;  // 32
    for (int kc = 0; kc < NC; kc++) {
        const int ls = kc & 1;
        // convert + store latent slab kc (consumes rl)
        char* Ls = smem + ls * L_STAGE;
#pragma unroll
        for (int q = 0; q < 4; q++) {
            __nv_bfloat162 h0 = __floats2bfloat162_rn(rl[q].x, rl[q].y);
            __nv_bfloat162 h1 = __floats2bfloat162_rn(rl[q].z, rl[q].w);
            uint2 pv;
            pv.x = reinterpret_cast<unsigned&>(h0);
            pv.y = reinterpret_cast<unsigned&>(h1);
            *reinterpret_cast<uint2*>(Ls + lso[q]) = pv;
        }
        // HOIST: issue latent LDG for slab kc+1 before the wait+barrier
        // (targets registers only; prior value consumed by the STS above)
        if (kc + 1 < NC) {
            const unsigned k0 = (unsigned)(kc + 1) * KT * 4;   // byte advance
#pragma unroll
            for (int q = 0; q < 4; q++)
                rl[q] = *reinterpret_cast<const float4*>(latb + lgo[q] + k0);
        }
        CP_WAIT0();          // A slab kc resident
        __syncthreads();     // + all LDSM of slab kc-1 complete

        // A stage (kc+1)&1 last read by MMA(kc-1); ordered by the sync above
        if (kc + 1 < NC) ISSUE_A(kc + 1);

        const unsigned lb = lmb + ls * L_STAGE;
        const unsigned ab = amb + ls * A_STAGE;
#pragma unroll
        for (int ks = 0; ks < 8; ks++) {
            unsigned a[4], b0[4], b1[4];
            ldsm4(a,  lb + ks * 32);
            ldsm4(b0, ab + ks * 32);
            ldsm4(b1, ab + 16 * SKB + ks * 32);
            mma_bf16(acc[0], a, b0[0], b0[1]);
            mma_bf16(acc[1], a, b0[2], b0[3]);
            mma_bf16(acc[2], a, b1[0], b1[1]);
            mma_bf16(acc[3], a, b1[2], b1[3]);
        }
        // no tail sync: next STS targets the other L stage; A issue ordered by next sync
    }
    __syncthreads();   // all MMA smem reads done before aliasing C over the buffers

    // --- epilogue: C -> smem (padded), ballot sign-pack, key + hash ---
    float*    Cs  = reinterpret_cast<float*>(smem);
    unsigned* wsm = reinterpret_cast<unsigned*>(smem + WSM_OFF);
    const int g = lane >> 2, tig = lane & 3;
#pragma unroll
    for (int ni = 0; ni < 4; ni++) {
        int row = wm * 16 + g;
        int col = wn * 32 + ni * 8 + 2 * tig;
        *reinterpret_cast<float2*>(&Cs[row * CS_STRIDE + col])       = make_float2(acc[ni][0], acc[ni][1]);
        *reinterpret_cast<float2*>(&Cs[(row + 8) * CS_STRIDE + col]) = make_float2(acc[ni][2], acc[ni][3]);
    }
    __syncthreads();

    // 256 words (64 rows x 4); 16 warps x 16 words; ballot packs 32 signs/instr
#pragma unroll
    for (int t = 0; t < 16; t++) {
        int idx = wid * 16 + t;
        int row = idx >> 2, w = idx & 3;
        unsigned bits = __ballot_sync(0xffffffffu, Cs[row * CS_STRIDE + w * 32 + lane] > 0.0f);
        if (lane == 0) {
            wsm[idx] = bits;
            reinterpret_cast<unsigned*>(g_keys)[(size_t)(rowBase + row) * 4 + w] = bits;
        }
    }
    __syncthreads();

    if (tid < BM) {
        unsigned w0 = wsm[tid * 4 + 0], w1 = wsm[tid * 4 + 1];
        unsigned w2 = wsm[tid * 4 + 2], w3 = wsm[tid * 4 + 3];
        unsigned h = w0 * 0x9E3779B1u;
        h ^= w1; h *= 0x85EBCA77u;
        h ^= w2; h *= 0xC2B2AE3Du;
        h ^= w3; h *= 0x27D4EB2Fu;
        h ^= h >> 15;
        g_hash[rowBase + tid] = h;
    }
}

// Stage 2: tile-parallel prefix-duplicate count + fused finalize.
// Block (tj, ti), tj<=ti. Row-tile ti has ti+1 contributing blocks; the last
// one (fence + per-tile done counter, ONE atomic per block) writes rsqrt.
// This exact handshake ran correctly through R12's full replay validation.
__global__ __launch_bounds__(TI, 8)
void count_tile_kernel(float* __restrict__ out) {
    const int ti = blockIdx.y, tj = blockIdx.x;
    if (tj > ti) return;

    __shared__ __align__(16) unsigned shh[TI];
    __shared__ int sh_last;
    const int tid   = threadIdx.x;
    const int i     = ti * TI + tid;
    const int jbase = tj * TI;

    shh[tid] = g_hash[jbase + tid];
    const unsigned hi = g_hash[i];
    const uint4    ki = g_keys[i];
    __syncthreads();

    const int lim = (ti == tj) ? (tid + 1) : TI;
    const int l4  = lim & ~3;
    int cnt = 0;

    const uint4* sh4 = reinterpret_cast<const uint4*>(shh);
    for (int j = 0; j < l4; j += 4) {
        uint4 hv = sh4[j >> 2];
        if (hv.x == hi) { uint4 kj = g_keys[jbase + j    ]; cnt += (kj.x==ki.x && kj.y==ki.y && kj.z==ki.z && kj.w==ki.w); }
        if (hv.y == hi) { uint4 kj = g_keys[jbase + j + 1]; cnt += (kj.x==ki.x && kj.y==ki.y && kj.z==ki.z && kj.w==ki.w); }
        if (hv.z == hi) { uint4 kj = g_keys[jbase + j + 2]; cnt += (kj.x==ki.x && kj.y==ki.y && kj.z==ki.z && kj.w==ki.w); }
        if (hv.w == hi) { uint4 kj = g_keys[jbase + j + 3]; cnt += (kj.x==ki.x && kj.y==ki.y && kj.z==ki.z && kj.w==ki.w); }
    }
    for (int j = l4; j < lim; j++) {
        if (shh[j] == hi) {
            uint4 kj = g_keys[jbase + j];
            cnt += (kj.x==ki.x && kj.y==ki.y && kj.z==ki.z && kj.w==ki.w);
        }
    }

    if (cnt) atomicAdd(&g_cnt[i], cnt);
    __threadfence();                 // order my count update before the done handshake
    __syncthreads();
    if (tid == 0) sh_last = (atomicAdd(&g_tile_done[ti], 1) == ti);
    __syncthreads();
    if (sh_last) {                   // all ti+1 contributors done -> counts final
        int c = *(volatile int*)&g_cnt[i];
        out[i] = rsqrtf((float)c);
    }
}

extern "C" void kernel_launch(void* const* d_in, const int* in_sizes, int n_in,
                              void* d_out, int out_size) {
    const float* lat  = (const float*)d_in[0];   // [128,64,4096]
    const float* Amat = (const float*)d_in[1];   // [128,4096]
    float* out = (float*)d_out;                  // [T,B] fp32

    cudaFuncSetAttribute(gemm_sign_kernel,
                         cudaFuncAttributeMaxDynamicSharedMemorySize, SMEM_BYTES);

    convertA_kernel<<<(128 * DIMK / 4) / 256, 256>>>(Amat);
    gemm_sign_kernel<<<N_ROWS / BM, NTHR, SMEM_BYTES>>>(lat);
    dim3 cgrid(N_ROWS / TI, N_ROWS / TI);
    count_tile_kernel<<<cgrid, TI>>>(out);
}